// round 1
// baseline (speedup 1.0000x reference)
#include <cuda_runtime.h>
#include <cstdint>

// Problem constants (fixed for this instance)
#define Bb 16
#define Ss 2048
#define Dd 1024
#define Hh 1024
#define Mm (Bb*Ss)      // 32768 rows
#define N3 (3*Hh)       // 3072 cols

// Scratch (static __device__ arrays: allowed; no runtime allocation)
__device__ float g_z[(size_t)Mm*Hh];   // tanh(z-gate)
__device__ float g_f[(size_t)Mm*Hh];   // sigmoid(f-gate)
__device__ float g_o[(size_t)Mm*Hh];   // sigmoid(o-gate)

__device__ __forceinline__ uint32_t f2tf32(float x){
  uint32_t u; asm("cvt.rna.tf32.f32 %0, %1;" : "=r"(u) : "f"(x)); return u;
}

__device__ __forceinline__ void mma_tf32(float* c, const uint32_t* a, const uint32_t* b){
  asm volatile("mma.sync.aligned.m16n8k8.row.col.f32.tf32.tf32.f32 "
    "{%0,%1,%2,%3}, {%4,%5,%6,%7}, {%8,%9}, {%0,%1,%2,%3};"
    : "+f"(c[0]),"+f"(c[1]),"+f"(c[2]),"+f"(c[3])
    : "r"(a[0]),"r"(a[1]),"r"(a[2]),"r"(a[3]),"r"(b[0]),"r"(b[1]));
}

constexpr int BM=128, BN=128, BK=16;
constexpr int KT = Dd/BK;       // 64 k-tiles
constexpr int LDK = BK + 4;     // pad 20 floats: conflict-free fragment LDS

__global__ __launch_bounds__(256,2) void gemm_gates_kernel(
    const float* __restrict__ A,    // [Mm, Dd]
    const float* __restrict__ W,    // [N3, Dd]
    const float* __restrict__ bias) // [N3]
{
  __shared__ uint32_t As[2][BM][LDK];
  __shared__ uint32_t Bs[2][BN][LDK];

  const int tid  = threadIdx.x;
  const int lane = tid & 31;
  const int warp = tid >> 5;
  const int wm = warp >> 2;        // 0..1  (64-row slabs)
  const int wn = warp & 3;         // 0..3  (32-col slabs)
  const int bm = blockIdx.y * BM;
  const int bn = blockIdx.x * BN;

  const int lrow = tid >> 2;        // 0..63
  const int lcol = (tid & 3) * 4;   // 0,4,8,12

  float acc[4][4][4];
  #pragma unroll
  for (int i=0;i<4;i++)
    #pragma unroll
    for (int j=0;j<4;j++)
      #pragma unroll
      for (int k=0;k<4;k++) acc[i][j][k]=0.f;

  float4 ra[2], rb[2];

  auto ldg_tile = [&](int kt){
    const float* ap = A + (size_t)(bm + lrow)*Dd + kt*BK + lcol;
    const float* bp = W + (size_t)(bn + lrow)*Dd + kt*BK + lcol;
    ra[0] = *(const float4*)ap;
    ra[1] = *(const float4*)(ap + (size_t)64*Dd);
    rb[0] = *(const float4*)bp;
    rb[1] = *(const float4*)(bp + (size_t)64*Dd);
  };

  auto sts_tile = [&](int buf){
    #pragma unroll
    for (int i=0;i<2;i++){
      uint4 pa, pb;
      pa.x=f2tf32(ra[i].x); pa.y=f2tf32(ra[i].y); pa.z=f2tf32(ra[i].z); pa.w=f2tf32(ra[i].w);
      pb.x=f2tf32(rb[i].x); pb.y=f2tf32(rb[i].y); pb.z=f2tf32(rb[i].z); pb.w=f2tf32(rb[i].w);
      *(uint4*)&As[buf][lrow+64*i][lcol] = pa;
      *(uint4*)&Bs[buf][lrow+64*i][lcol] = pb;
    }
  };

  auto compute = [&](int buf){
    #pragma unroll
    for (int ks=0; ks<2; ks++){
      uint32_t af[4][4], bf[4][2];
      const int kc = ks*8 + (lane & 3);
      const int rA = wm*64 + (lane>>2);
      #pragma unroll
      for (int mi=0;mi<4;mi++){
        af[mi][0]=As[buf][rA+mi*16    ][kc  ];
        af[mi][1]=As[buf][rA+mi*16 + 8][kc  ];
        af[mi][2]=As[buf][rA+mi*16    ][kc+4];
        af[mi][3]=As[buf][rA+mi*16 + 8][kc+4];
      }
      const int rB = wn*32 + (lane>>2);
      #pragma unroll
      for (int ni=0;ni<4;ni++){
        bf[ni][0]=Bs[buf][rB+ni*8][kc  ];
        bf[ni][1]=Bs[buf][rB+ni*8][kc+4];
      }
      #pragma unroll
      for (int mi=0;mi<4;mi++)
        #pragma unroll
        for (int ni=0;ni<4;ni++)
          mma_tf32(acc[mi][ni], af[mi], bf[ni]);
    }
  };

  ldg_tile(0); sts_tile(0); __syncthreads();
  for (int kt=0; kt<KT; kt++){
    const int cur = kt & 1;
    if (kt+1 < KT) ldg_tile(kt+1);
    compute(cur);
    if (kt+1 < KT) sts_tile((kt+1)&1);
    __syncthreads();
  }

  // Epilogue: bias + activation, scatter into gate-specific scratch.
  // Whole block lies in one gate (bn multiple of 128, gates at 1024 bounds).
  const int gate = bn >> 10;
  float* dst = (gate==0) ? g_z : ((gate==1) ? g_f : g_o);
  const int r0 = bm + wm*64 + (lane>>2);
  const int c0 = bn + wn*32 + (lane&3)*2;
  #pragma unroll
  for (int mi=0;mi<4;mi++){
    #pragma unroll
    for (int ni=0;ni<4;ni++){
      #pragma unroll
      for (int half=0; half<2; half++){
        const int row = r0 + mi*16 + half*8;
        const int col = c0 + ni*8;
        float y0 = acc[mi][ni][half*2+0] + bias[col];
        float y1 = acc[mi][ni][half*2+1] + bias[col+1];
        float v0, v1;
        if (gate==0){ v0 = tanhf(y0); v1 = tanhf(y1); }
        else        { v0 = 1.f/(1.f+__expf(-y0)); v1 = 1.f/(1.f+__expf(-y1)); }
        const int hcol = col & (Hh-1);
        *(float2*)&dst[(size_t)row*Hh + hcol] = make_float2(v0, v1);
      }
    }
  }
}

// Serial linear recurrence per (b,h) chain + fused output gate + c_last.
__global__ __launch_bounds__(256) void scan_kernel(
    float* __restrict__ out, float* __restrict__ clast, int write_clast)
{
  const int t = blockIdx.x*blockDim.x + threadIdx.x;   // 0..Bb*Hh-1
  const int b  = t >> 10;        // / Hh
  const int hh = t & (Hh-1);
  const size_t base = (size_t)b*Ss*Hh + hh;
  float h = 0.f;
  #pragma unroll 8
  for (int s=0; s<Ss; s++){
    const size_t idx = base + (size_t)s*Hh;
    const float z = g_z[idx];
    const float f = g_f[idx];
    const float o = g_o[idx];
    h = fmaf(f, z - h, h);       // f*z + (1-f)*h
    out[idx] = o * h;
  }
  if (write_clast) clast[(size_t)b*Hh + hh] = h;
}

extern "C" void kernel_launch(void* const* d_in, const int* in_sizes, int n_in,
                              void* d_out, int out_size) {
  const float* inp  = (const float*)d_in[0];   // [16,2048,1024] f32
  const float* W    = (const float*)d_in[1];   // [3072,1024]  f32
  const float* bias = (const float*)d_in[2];   // [3072]       f32
  float* out = (float*)d_out;

  dim3 grid(N3/BN, Mm/BM);   // (24, 256)
  gemm_gates_kernel<<<grid, 256>>>(inp, W, bias);

  const int write_clast = (out_size >= Mm*Hh + Bb*Hh) ? 1 : 0;
  scan_kernel<<<(Bb*Hh)/256, 256>>>(out, out + (size_t)Mm*Hh, write_clast);
}

// round 3
// speedup vs baseline: 1.4944x; 1.4944x over previous
#include <cuda_runtime.h>
#include <cstdint>
#include <cstddef>

#define Bb 16
#define Ss 2048
#define Dd 1024
#define Hh 1024
#define Mm (Bb*Ss)      // 32768
#define N3 (3*Hh)       // 3072
#define SC 16
#define CH (Ss/SC)      // 128

// ---- device scratch (static: allowed) ----
__device__ float g_z[(size_t)Mm*Hh];
__device__ float g_f[(size_t)Mm*Hh];
__device__ float g_o[(size_t)Mm*Hh];
__device__ float g_Ar[(size_t)Mm*Dd];   // tf32-rounded A
__device__ float g_Wr[(size_t)N3*Dd];   // tf32-rounded W
__device__ float g_Ac[Bb*SC*Hh];
__device__ float g_Bc[Bb*SC*Hh];
__device__ float g_hs[Bb*SC*Hh];

__device__ __forceinline__ uint32_t smem_u32(const void* p){
  uint32_t a;
  asm("{ .reg .u64 t; cvta.to.shared.u64 t, %1; cvt.u32.u64 %0, t; }" : "=r"(a) : "l"(p));
  return a;
}

__device__ __forceinline__ void mma_tf32(float* c, const uint32_t* a, const uint32_t* b){
  asm volatile("mma.sync.aligned.m16n8k8.row.col.f32.tf32.tf32.f32 "
    "{%0,%1,%2,%3}, {%4,%5,%6,%7}, {%8,%9}, {%0,%1,%2,%3};"
    : "+f"(c[0]),"+f"(c[1]),"+f"(c[2]),"+f"(c[3])
    : "r"(a[0]),"r"(a[1]),"r"(a[2]),"r"(a[3]),"r"(b[0]),"r"(b[1]));
}

// ---- tf32 pre-round ----
__global__ void round_tf32_k(const uint4* __restrict__ src, uint4* __restrict__ dst, int n4){
  int i = blockIdx.x*blockDim.x + threadIdx.x;
  if (i >= n4) return;
  uint4 v = src[i]; uint4 u;
  asm("cvt.rna.tf32.f32 %0, %1;" : "=r"(u.x) : "f"(__uint_as_float(v.x)));
  asm("cvt.rna.tf32.f32 %0, %1;" : "=r"(u.y) : "f"(__uint_as_float(v.y)));
  asm("cvt.rna.tf32.f32 %0, %1;" : "=r"(u.z) : "f"(__uint_as_float(v.z)));
  asm("cvt.rna.tf32.f32 %0, %1;" : "=r"(u.w) : "f"(__uint_as_float(v.w)));
  dst[i] = u;
}

// ---- GEMM: 128x128x(BK=32) tiles, cp.async 3-stage, ldmatrix fragments ----
constexpr int BM=128, BN=128, BK=32;
constexpr int KT = Dd/BK;              // 32 k-tiles
constexpr int ROWF = 36;               // floats per smem row (32 + 4 pad) = 144B
constexpr int STG_F = BM*ROWF;         // 4608 floats per operand per stage
constexpr int STAGE_F = 2*STG_F;       // 9216 floats (A then B)
constexpr int GEMM_SMEM = 3*STAGE_F*4; // 110592 bytes

__global__ __launch_bounds__(256,2) void gemm_qrnn(
    const float* __restrict__ A,    // g_Ar [Mm, Dd]
    const float* __restrict__ W,    // g_Wr [N3, Dd]
    const float* __restrict__ bias)
{
  extern __shared__ float sm[];
  const int tid  = threadIdx.x;
  const int lane = tid & 31;
  const int warp = tid >> 5;
  const int wm = warp >> 2;       // 0..1
  const int wn = warp & 3;        // 0..3
  const int bm = blockIdx.y * BM;
  const int bn = blockIdx.x * BN;
  const uint32_t smb = smem_u32(sm);

  float acc[4][4][4];
  #pragma unroll
  for (int i=0;i<4;i++)
    #pragma unroll
    for (int j=0;j<4;j++)
      #pragma unroll
      for (int k=0;k<4;k++) acc[i][j][k]=0.f;

  auto issue = [&](int kt, int s){
    float* as = sm + s*STAGE_F;
    float* bs = as + STG_F;
    #pragma unroll
    for (int i=0;i<4;i++){
      int idx = tid + i*256;           // 0..1023
      int row = idx >> 3;              // 0..127
      int c16 = idx & 7;               // 16B chunk within 32-float row
      const float* ga = A + (size_t)(bm+row)*Dd + kt*BK + c16*4;
      const float* gb = W + (size_t)(bn+row)*Dd + kt*BK + c16*4;
      uint32_t sa = smem_u32(as + row*ROWF + c16*4);
      uint32_t sb = smem_u32(bs + row*ROWF + c16*4);
      asm volatile("cp.async.cg.shared.global [%0], [%1], 16;" :: "r"(sa), "l"(ga));
      asm volatile("cp.async.cg.shared.global [%0], [%1], 16;" :: "r"(sb), "l"(gb));
    }
  };

  auto compute = [&](int s){
    const uint32_t abase = smb + s*(STAGE_F*4);
    const uint32_t bbase = abase + STG_F*4;
    #pragma unroll
    for (int q=0; q<4; q++){           // 4 k8 chunks in BK=32
      uint32_t a[4][4], b[4][2];
      #pragma unroll
      for (int mi=0;mi<4;mi++){
        int rowA = wm*64 + mi*16 + (lane & 15);
        uint32_t addr = abase + rowA*144 + q*32 + (lane>>4)*16;
        asm volatile("ldmatrix.sync.aligned.m8n8.x4.shared.b16 {%0,%1,%2,%3}, [%4];"
          : "=r"(a[mi][0]),"=r"(a[mi][1]),"=r"(a[mi][2]),"=r"(a[mi][3]) : "r"(addr));
      }
      #pragma unroll
      for (int np=0; np<2; np++){
        int rowB = wn*32 + np*16 + (lane & 7) + ((lane>>4)&1)*8;
        uint32_t addr = bbase + rowB*144 + q*32 + ((lane>>3)&1)*16;
        asm volatile("ldmatrix.sync.aligned.m8n8.x4.shared.b16 {%0,%1,%2,%3}, [%4];"
          : "=r"(b[np*2][0]),"=r"(b[np*2][1]),"=r"(b[np*2+1][0]),"=r"(b[np*2+1][1]) : "r"(addr));
      }
      #pragma unroll
      for (int mi=0;mi<4;mi++)
        #pragma unroll
        for (int ni=0;ni<4;ni++)
          mma_tf32(acc[mi][ni], a[mi], b[ni]);
    }
  };

  issue(0,0); asm volatile("cp.async.commit_group;" ::: "memory");
  issue(1,1); asm volatile("cp.async.commit_group;" ::: "memory");

  for (int kt=0; kt<KT; kt++){
    asm volatile("cp.async.wait_group 1;" ::: "memory");
    __syncthreads();
    if (kt+2 < KT) issue(kt+2, (kt+2)%3);
    asm volatile("cp.async.commit_group;" ::: "memory");
    compute(kt%3);
  }

  // Epilogue: bias + activation, direct scatter into gate scratch.
  const int gate = bn >> 10;           // 128-col tile lies within one gate
  float* dst = (gate==0) ? g_z : ((gate==1) ? g_f : g_o);
  const int r0 = bm + wm*64 + (lane>>2);
  const int c0 = bn + wn*32 + (lane&3)*2;
  #pragma unroll
  for (int mi=0;mi<4;mi++){
    #pragma unroll
    for (int ni=0;ni<4;ni++){
      #pragma unroll
      for (int half=0; half<2; half++){
        const int row = r0 + mi*16 + half*8;
        const int col = c0 + ni*8;
        float y0 = acc[mi][ni][half*2+0] + __ldg(&bias[col]);
        float y1 = acc[mi][ni][half*2+1] + __ldg(&bias[col+1]);
        float v0, v1;
        if (gate==0){ v0 = tanhf(y0); v1 = tanhf(y1); }
        else        { v0 = __fdividef(1.f, 1.f+__expf(-y0));
                      v1 = __fdividef(1.f, 1.f+__expf(-y1)); }
        const int hcol = col & (Hh-1);
        *(float2*)&dst[(size_t)row*Hh + hcol] = make_float2(v0, v1);
      }
    }
  }
}

// ---- two-pass chunked scan ----
__global__ __launch_bounds__(1024) void scanA_k(){
  int b = blockIdx.x >> 4, c = blockIdx.x & 15, h = threadIdx.x;
  size_t base = ((size_t)(b*Ss + c*CH))*Hh + h;
  float A = 1.f, hh = 0.f;
  #pragma unroll 4
  for (int s=0; s<CH; s++){
    float f = g_f[base + (size_t)s*Hh];
    float z = g_z[base + (size_t)s*Hh];
    hh = fmaf(f, z - hh, hh);
    A *= (1.f - f);
  }
  int o = blockIdx.x*Hh + h;
  g_Ac[o] = A; g_Bc[o] = hh;
}

__global__ __launch_bounds__(1024) void scanB_k(float* __restrict__ clast, int wr){
  int t = blockIdx.x*blockDim.x + threadIdx.x;   // 16384
  int b = t >> 10, h = t & (Hh-1);
  float hh = 0.f;
  #pragma unroll
  for (int c=0; c<SC; c++){
    int idx = (b*SC + c)*Hh + h;
    g_hs[idx] = hh;
    hh = fmaf(g_Ac[idx], hh, g_Bc[idx]);
  }
  if (wr) clast[t] = hh;
}

__global__ __launch_bounds__(1024) void scanC_k(float* __restrict__ out){
  int b = blockIdx.x >> 4, c = blockIdx.x & 15, h = threadIdx.x;
  size_t base = ((size_t)(b*Ss + c*CH))*Hh + h;
  float hh = g_hs[blockIdx.x*Hh + h];
  #pragma unroll 4
  for (int s=0; s<CH; s++){
    size_t idx = base + (size_t)s*Hh;
    float f = g_f[idx];
    float z = g_z[idx];
    float o = g_o[idx];
    hh = fmaf(f, z - hh, hh);
    out[idx] = o * hh;
  }
}

// ---- host ----
extern "C" void kernel_launch(void* const* d_in, const int* in_sizes, int n_in,
                              void* d_out, int out_size) {
  const float* inp  = (const float*)d_in[0];
  const float* W    = (const float*)d_in[1];
  const float* bias = (const float*)d_in[2];
  float* out = (float*)d_out;

  void *pA=nullptr, *pW=nullptr;
  cudaGetSymbolAddress(&pA, g_Ar);
  cudaGetSymbolAddress(&pW, g_Wr);

  int nA4 = Mm*Dd/4, nW4 = N3*Dd/4;
  round_tf32_k<<<(nA4+255)/256, 256>>>((const uint4*)inp, (uint4*)pA, nA4);
  round_tf32_k<<<(nW4+255)/256, 256>>>((const uint4*)W,   (uint4*)pW, nW4);

  static int smem_set = 0;
  if (!smem_set){
    cudaFuncSetAttribute(gemm_qrnn, cudaFuncAttributeMaxDynamicSharedMemorySize, GEMM_SMEM);
    smem_set = 1;
  }
  gemm_qrnn<<<dim3(N3/BN, Mm/BM), 256, GEMM_SMEM>>>((const float*)pA, (const float*)pW, bias);

  scanA_k<<<Bb*SC, 1024>>>();
  int wr = (out_size >= Mm*Hh + Bb*Hh) ? 1 : 0;
  scanB_k<<<Bb*Hh/1024, 1024>>>(out + (size_t)Mm*Hh, wr);
  scanC_k<<<Bb*SC, 1024>>>(out);
}

// round 4
// speedup vs baseline: 1.6702x; 1.1176x over previous
#include <cuda_runtime.h>
#include <cuda_fp16.h>
#include <cstdint>
#include <cstddef>

#define Bb 16
#define Ss 2048
#define Dd 1024
#define Hh 1024
#define Mm (Bb*Ss)      // 32768
#define N3 (3*Hh)       // 3072
#define SC 16
#define CH (Ss/SC)      // 128

// ---- device scratch (static: allowed) ----
__device__ float  g_z[(size_t)Mm*Hh];
__device__ float  g_f[(size_t)Mm*Hh];
__device__ float  g_o[(size_t)Mm*Hh];
__device__ __half g_Ah[(size_t)Mm*Dd];
__device__ __half g_Wh[(size_t)N3*Dd];
__device__ float  g_Ac[Bb*SC*Hh];
__device__ float  g_Bc[Bb*SC*Hh];
__device__ float  g_hs[Bb*SC*Hh];

__device__ __forceinline__ uint32_t smem_u32(const void* p){
  uint32_t a;
  asm("{ .reg .u64 t; cvta.to.shared.u64 t, %1; cvt.u32.u64 %0, t; }" : "=r"(a) : "l"(p));
  return a;
}

__device__ __forceinline__ void mma_f16(float* c, const uint32_t* a, const uint32_t* b){
  asm volatile("mma.sync.aligned.m16n8k16.row.col.f32.f16.f16.f32 "
    "{%0,%1,%2,%3}, {%4,%5,%6,%7}, {%8,%9}, {%0,%1,%2,%3};"
    : "+f"(c[0]),"+f"(c[1]),"+f"(c[2]),"+f"(c[3])
    : "r"(a[0]),"r"(a[1]),"r"(a[2]),"r"(a[3]),"r"(b[0]),"r"(b[1]));
}

// ---- f32 -> f16 convert (8 floats -> 8 halves per thread) ----
__global__ void to_half_k(const float4* __restrict__ src, uint4* __restrict__ dst, int n8){
  int i = blockIdx.x*blockDim.x + threadIdx.x;
  if (i >= n8) return;
  float4 v0 = src[2*i], v1 = src[2*i+1];
  __half2 h0 = __floats2half2_rn(v0.x, v0.y);
  __half2 h1 = __floats2half2_rn(v0.z, v0.w);
  __half2 h2 = __floats2half2_rn(v1.x, v1.y);
  __half2 h3 = __floats2half2_rn(v1.z, v1.w);
  uint4 u;
  u.x = *(uint32_t*)&h0; u.y = *(uint32_t*)&h1;
  u.z = *(uint32_t*)&h2; u.w = *(uint32_t*)&h3;
  dst[i] = u;
}

// ---- GEMM: 128x128x(BK=32) fp16 tiles, cp.async 4-stage, ldmatrix ----
constexpr int BM=128, BN=128, BK=32;
constexpr int KT = Dd/BK;               // 32 k-tiles
constexpr int ROWH = 40;                // halves per smem row (32 + 8 pad) = 80B (odd 16B stride)
constexpr int STG_H = BM*ROWH;          // 5120 halves per operand per stage
constexpr int STAGE_H = 2*STG_H;        // 10240 halves = 20480B per stage
constexpr int NSTG = 4;
constexpr int GEMM_SMEM = NSTG*STAGE_H*2;  // 81920 bytes

__global__ __launch_bounds__(256,2) void gemm_qrnn(
    const __half* __restrict__ A,   // g_Ah [Mm, Dd]
    const __half* __restrict__ W,   // g_Wh [N3, Dd]
    const float* __restrict__ bias)
{
  extern __shared__ __half sm[];
  const int tid  = threadIdx.x;
  const int lane = tid & 31;
  const int warp = tid >> 5;
  const int wm = warp >> 2;       // 0..1
  const int wn = warp & 3;        // 0..3
  const int bm = blockIdx.y * BM;
  const int bn = blockIdx.x * BN;
  const uint32_t smb = smem_u32(sm);

  float acc[4][4][4];
  #pragma unroll
  for (int i=0;i<4;i++)
    #pragma unroll
    for (int j=0;j<4;j++)
      #pragma unroll
      for (int k=0;k<4;k++) acc[i][j][k]=0.f;

  auto issue = [&](int kt, int s){
    __half* as = sm + s*STAGE_H;
    __half* bs = as + STG_H;
    #pragma unroll
    for (int i=0;i<2;i++){
      int idx = tid + i*256;            // 0..511 : row 0..127, chunk 0..3
      int row = idx >> 2;
      int ch  = idx & 3;                // 16B chunk = 8 halves
      const __half* ga = A + (size_t)(bm+row)*Dd + kt*BK + ch*8;
      const __half* gb = W + (size_t)(bn+row)*Dd + kt*BK + ch*8;
      uint32_t sa = smem_u32(as + row*ROWH + ch*8);
      uint32_t sb = smem_u32(bs + row*ROWH + ch*8);
      asm volatile("cp.async.cg.shared.global [%0], [%1], 16;" :: "r"(sa), "l"(ga));
      asm volatile("cp.async.cg.shared.global [%0], [%1], 16;" :: "r"(sb), "l"(gb));
    }
  };

  auto compute = [&](int s){
    const uint32_t abase = smb + s*(STAGE_H*2);
    const uint32_t bbase = abase + STG_H*2;
    #pragma unroll
    for (int q=0; q<2; q++){            // 2 k16 chunks in BK=32
      uint32_t a[4][4], b[4][2];
      #pragma unroll
      for (int mi=0;mi<4;mi++){
        int rowA = wm*64 + mi*16 + (lane & 15);
        uint32_t addr = abase + rowA*80 + q*32 + (lane>>4)*16;
        asm volatile("ldmatrix.sync.aligned.m8n8.x4.shared.b16 {%0,%1,%2,%3}, [%4];"
          : "=r"(a[mi][0]),"=r"(a[mi][1]),"=r"(a[mi][2]),"=r"(a[mi][3]) : "r"(addr));
      }
      #pragma unroll
      for (int np=0; np<2; np++){
        int rowB = wn*32 + np*16 + (lane & 7) + ((lane>>4)&1)*8;
        uint32_t addr = bbase + rowB*80 + q*32 + ((lane>>3)&1)*16;
        asm volatile("ldmatrix.sync.aligned.m8n8.x4.shared.b16 {%0,%1,%2,%3}, [%4];"
          : "=r"(b[np*2][0]),"=r"(b[np*2][1]),"=r"(b[np*2+1][0]),"=r"(b[np*2+1][1]) : "r"(addr));
      }
      #pragma unroll
      for (int mi=0;mi<4;mi++)
        #pragma unroll
        for (int ni=0;ni<4;ni++)
          mma_f16(acc[mi][ni], a[mi], b[ni]);
    }
  };

  issue(0,0); asm volatile("cp.async.commit_group;" ::: "memory");
  issue(1,1); asm volatile("cp.async.commit_group;" ::: "memory");
  issue(2,2); asm volatile("cp.async.commit_group;" ::: "memory");

  for (int kt=0; kt<KT; kt++){
    asm volatile("cp.async.wait_group 2;" ::: "memory");
    __syncthreads();
    if (kt+3 < KT) issue(kt+3, (kt+3)%NSTG);
    asm volatile("cp.async.commit_group;" ::: "memory");
    compute(kt%NSTG);
  }

  // Epilogue: bias + activation, direct scatter into gate scratch.
  const int gate = bn >> 10;            // 128-col tile lies within one gate
  float* dst = (gate==0) ? g_z : ((gate==1) ? g_f : g_o);
  const int r0 = bm + wm*64 + (lane>>2);
  const int c0 = bn + wn*32 + (lane&3)*2;
  #pragma unroll
  for (int mi=0;mi<4;mi++){
    #pragma unroll
    for (int ni=0;ni<4;ni++){
      #pragma unroll
      for (int half=0; half<2; half++){
        const int row = r0 + mi*16 + half*8;
        const int col = c0 + ni*8;
        float y0 = acc[mi][ni][half*2+0] + __ldg(&bias[col]);
        float y1 = acc[mi][ni][half*2+1] + __ldg(&bias[col+1]);
        float v0, v1;
        if (gate==0){ v0 = tanhf(y0); v1 = tanhf(y1); }
        else        { v0 = __fdividef(1.f, 1.f+__expf(-y0));
                      v1 = __fdividef(1.f, 1.f+__expf(-y1)); }
        const int hcol = col & (Hh-1);
        *(float2*)&dst[(size_t)row*Hh + hcol] = make_float2(v0, v1);
      }
    }
  }
}

// ---- two-pass chunked scan ----
__global__ __launch_bounds__(1024) void scanA_k(){
  int b = blockIdx.x >> 4, c = blockIdx.x & 15, h = threadIdx.x;
  size_t base = ((size_t)(b*Ss + c*CH))*Hh + h;
  float A = 1.f, hh = 0.f;
  #pragma unroll 4
  for (int s=0; s<CH; s++){
    float f = g_f[base + (size_t)s*Hh];
    float z = g_z[base + (size_t)s*Hh];
    hh = fmaf(f, z - hh, hh);
    A *= (1.f - f);
  }
  int o = blockIdx.x*Hh + h;
  g_Ac[o] = A; g_Bc[o] = hh;
}

__global__ __launch_bounds__(1024) void scanB_k(float* __restrict__ clast, int wr){
  int t = blockIdx.x*blockDim.x + threadIdx.x;   // 16384
  int b = t >> 10, h = t & (Hh-1);
  float hh = 0.f;
  #pragma unroll
  for (int c=0; c<SC; c++){
    int idx = (b*SC + c)*Hh + h;
    g_hs[idx] = hh;
    hh = fmaf(g_Ac[idx], hh, g_Bc[idx]);
  }
  if (wr) clast[t] = hh;
}

__global__ __launch_bounds__(1024) void scanC_k(float* __restrict__ out){
  int b = blockIdx.x >> 4, c = blockIdx.x & 15, h = threadIdx.x;
  size_t base = ((size_t)(b*Ss + c*CH))*Hh + h;
  float hh = g_hs[blockIdx.x*Hh + h];
  #pragma unroll 4
  for (int s=0; s<CH; s++){
    size_t idx = base + (size_t)s*Hh;
    float f = g_f[idx];
    float z = g_z[idx];
    float o = g_o[idx];
    hh = fmaf(f, z - hh, hh);
    out[idx] = o * hh;
  }
}

// ---- host ----
extern "C" void kernel_launch(void* const* d_in, const int* in_sizes, int n_in,
                              void* d_out, int out_size) {
  const float* inp  = (const float*)d_in[0];
  const float* W    = (const float*)d_in[1];
  const float* bias = (const float*)d_in[2];
  float* out = (float*)d_out;

  void *pA=nullptr, *pW=nullptr;
  cudaGetSymbolAddress(&pA, g_Ah);
  cudaGetSymbolAddress(&pW, g_Wh);

  int nA8 = Mm*Dd/8, nW8 = N3*Dd/8;
  to_half_k<<<(nA8+255)/256, 256>>>((const float4*)inp, (uint4*)pA, nA8);
  to_half_k<<<(nW8+255)/256, 256>>>((const float4*)W,   (uint4*)pW, nW8);

  static int smem_set = 0;
  if (!smem_set){
    cudaFuncSetAttribute(gemm_qrnn, cudaFuncAttributeMaxDynamicSharedMemorySize, GEMM_SMEM);
    smem_set = 1;
  }
  gemm_qrnn<<<dim3(N3/BN, Mm/BM), 256, GEMM_SMEM>>>((const __half*)pA, (const __half*)pW, bias);

  scanA_k<<<Bb*SC, 1024>>>();
  int wr = (out_size >= Mm*Hh + Bb*Hh) ? 1 : 0;
  scanB_k<<<Bb*Hh/1024, 1024>>>(out + (size_t)Mm*Hh, wr);
  scanC_k<<<Bb*SC, 1024>>>(out);
}

// round 5
// speedup vs baseline: 2.5627x; 1.5344x over previous
#include <cuda_runtime.h>
#include <cuda_fp16.h>
#include <cstdint>
#include <cstddef>

#define Bb 16
#define Ss 2048
#define Dd 1024
#define Hh 1024
#define Mm (Bb*Ss)      // 32768
#define N3 (3*Hh)       // 3072
#define SC 16
#define CH (Ss/SC)      // 128

// ---- device scratch (static: allowed) ----
__device__ __half g_z[(size_t)Mm*Hh];
__device__ __half g_f[(size_t)Mm*Hh];
__device__ __half g_o[(size_t)Mm*Hh];
__device__ __half g_Ah[(size_t)Mm*Dd];
__device__ __half g_Wh[(size_t)N3*Dd];
__device__ float  g_Ac[Bb*SC*Hh];
__device__ float  g_Bc[Bb*SC*Hh];
__device__ float  g_hs[Bb*SC*Hh];

__device__ __forceinline__ uint32_t smem_u32(const void* p){
  uint32_t a;
  asm("{ .reg .u64 t; cvta.to.shared.u64 t, %1; cvt.u32.u64 %0, t; }" : "=r"(a) : "l"(p));
  return a;
}

__device__ __forceinline__ void mma_f16(float* c, const uint32_t* a, const uint32_t* b){
  asm volatile("mma.sync.aligned.m16n8k16.row.col.f32.f16.f16.f32 "
    "{%0,%1,%2,%3}, {%4,%5,%6,%7}, {%8,%9}, {%0,%1,%2,%3};"
    : "+f"(c[0]),"+f"(c[1]),"+f"(c[2]),"+f"(c[3])
    : "r"(a[0]),"r"(a[1]),"r"(a[2]),"r"(a[3]),"r"(b[0]),"r"(b[1]));
}

// ---- f32 -> f16 convert (8 floats -> 8 halves per thread) ----
__global__ void to_half_k(const float4* __restrict__ src, uint4* __restrict__ dst, int n8){
  int i = blockIdx.x*blockDim.x + threadIdx.x;
  if (i >= n8) return;
  float4 v0 = src[2*i], v1 = src[2*i+1];
  __half2 h0 = __floats2half2_rn(v0.x, v0.y);
  __half2 h1 = __floats2half2_rn(v0.z, v0.w);
  __half2 h2 = __floats2half2_rn(v1.x, v1.y);
  __half2 h3 = __floats2half2_rn(v1.z, v1.w);
  uint4 u;
  u.x = *(uint32_t*)&h0; u.y = *(uint32_t*)&h1;
  u.z = *(uint32_t*)&h2; u.w = *(uint32_t*)&h3;
  dst[i] = u;
}

// ---- GEMM: 128x128x(BK=32) fp16 tiles, cp.async 4-stage, ldmatrix ----
constexpr int BM=128, BN=128, BK=32;
constexpr int KT = Dd/BK;               // 32 k-tiles
constexpr int ROWH = 40;                // halves per smem row (32 + 8 pad) = 80B
constexpr int STG_H = BM*ROWH;          // 5120 halves per operand per stage
constexpr int STAGE_H = 2*STG_H;        // 10240 halves = 20480B per stage
constexpr int NSTG = 4;
constexpr int GEMM_SMEM = NSTG*STAGE_H*2;  // 81920 bytes

__global__ __launch_bounds__(256,2) void gemm_qrnn(
    const __half* __restrict__ A,   // g_Ah [Mm, Dd]
    const __half* __restrict__ W,   // g_Wh [N3, Dd]
    const float* __restrict__ bias)
{
  extern __shared__ __half sm[];
  const int tid  = threadIdx.x;
  const int lane = tid & 31;
  const int warp = tid >> 5;
  const int wm = warp >> 2;       // 0..1
  const int wn = warp & 3;        // 0..3
  const int bm = blockIdx.y * BM;
  const int bn = blockIdx.x * BN;
  const uint32_t smb = smem_u32(sm);

  float acc[4][4][4];
  #pragma unroll
  for (int i=0;i<4;i++)
    #pragma unroll
    for (int j=0;j<4;j++)
      #pragma unroll
      for (int k=0;k<4;k++) acc[i][j][k]=0.f;

  auto issue = [&](int kt, int s){
    __half* as = sm + s*STAGE_H;
    __half* bs = as + STG_H;
    #pragma unroll
    for (int i=0;i<2;i++){
      int idx = tid + i*256;            // 0..511 : row 0..127, chunk 0..3
      int row = idx >> 2;
      int ch  = idx & 3;
      const __half* ga = A + (size_t)(bm+row)*Dd + kt*BK + ch*8;
      const __half* gb = W + (size_t)(bn+row)*Dd + kt*BK + ch*8;
      uint32_t sa = smem_u32(as + row*ROWH + ch*8);
      uint32_t sb = smem_u32(bs + row*ROWH + ch*8);
      asm volatile("cp.async.cg.shared.global [%0], [%1], 16;" :: "r"(sa), "l"(ga));
      asm volatile("cp.async.cg.shared.global [%0], [%1], 16;" :: "r"(sb), "l"(gb));
    }
  };

  auto compute = [&](int s){
    const uint32_t abase = smb + s*(STAGE_H*2);
    const uint32_t bbase = abase + STG_H*2;
    #pragma unroll
    for (int q=0; q<2; q++){            // 2 k16 chunks in BK=32
      uint32_t a[4][4], b[4][2];
      #pragma unroll
      for (int mi=0;mi<4;mi++){
        int rowA = wm*64 + mi*16 + (lane & 15);
        uint32_t addr = abase + rowA*80 + q*32 + (lane>>4)*16;
        asm volatile("ldmatrix.sync.aligned.m8n8.x4.shared.b16 {%0,%1,%2,%3}, [%4];"
          : "=r"(a[mi][0]),"=r"(a[mi][1]),"=r"(a[mi][2]),"=r"(a[mi][3]) : "r"(addr));
      }
      #pragma unroll
      for (int np=0; np<2; np++){
        int rowB = wn*32 + np*16 + (lane & 7) + ((lane>>4)&1)*8;
        uint32_t addr = bbase + rowB*80 + q*32 + ((lane>>3)&1)*16;
        asm volatile("ldmatrix.sync.aligned.m8n8.x4.shared.b16 {%0,%1,%2,%3}, [%4];"
          : "=r"(b[np*2][0]),"=r"(b[np*2][1]),"=r"(b[np*2+1][0]),"=r"(b[np*2+1][1]) : "r"(addr));
      }
      #pragma unroll
      for (int mi=0;mi<4;mi++)
        #pragma unroll
        for (int ni=0;ni<4;ni++)
          mma_f16(acc[mi][ni], a[mi], b[ni]);
    }
  };

  issue(0,0); asm volatile("cp.async.commit_group;" ::: "memory");
  issue(1,1); asm volatile("cp.async.commit_group;" ::: "memory");
  issue(2,2); asm volatile("cp.async.commit_group;" ::: "memory");

  for (int kt=0; kt<KT; kt++){
    asm volatile("cp.async.wait_group 2;" ::: "memory");
    __syncthreads();
    if (kt+3 < KT) issue(kt+3, (kt+3)%NSTG);
    asm volatile("cp.async.commit_group;" ::: "memory");
    compute(kt%NSTG);
  }

  // Epilogue: bias + activation -> fp16 gate scratch (half2 stores).
  const int gate = bn >> 10;            // 128-col tile lies within one gate
  __half* dst = (gate==0) ? g_z : ((gate==1) ? g_f : g_o);
  const int r0 = bm + wm*64 + (lane>>2);
  const int c0 = bn + wn*32 + (lane&3)*2;
  #pragma unroll
  for (int mi=0;mi<4;mi++){
    #pragma unroll
    for (int ni=0;ni<4;ni++){
      #pragma unroll
      for (int half=0; half<2; half++){
        const int row = r0 + mi*16 + half*8;
        const int col = c0 + ni*8;
        float y0 = acc[mi][ni][half*2+0] + __ldg(&bias[col]);
        float y1 = acc[mi][ni][half*2+1] + __ldg(&bias[col+1]);
        float v0, v1;
        if (gate==0){ v0 = tanhf(y0); v1 = tanhf(y1); }
        else        { v0 = __fdividef(1.f, 1.f+__expf(-y0));
                      v1 = __fdividef(1.f, 1.f+__expf(-y1)); }
        const int hcol = col & (Hh-1);
        *(__half2*)&dst[(size_t)row*Hh + hcol] = __floats2half2_rn(v0, v1);
      }
    }
  }
}

// ---- two-pass chunked scan (half2 vectorized, f32 math) ----
__global__ __launch_bounds__(512) void scanA_k(){
  int b = blockIdx.x >> 4, c = blockIdx.x & 15, h2 = threadIdx.x;  // h = 2*h2
  size_t base2 = ((size_t)(b*Ss + c*CH))*(Hh/2) + h2;              // half2 index
  const __half2* Z = (const __half2*)g_z;
  const __half2* F = (const __half2*)g_f;
  float2 A = make_float2(1.f,1.f), hh = make_float2(0.f,0.f);
  #pragma unroll 4
  for (int s=0; s<CH; s++){
    float2 f = __half22float2(F[base2 + (size_t)s*(Hh/2)]);
    float2 z = __half22float2(Z[base2 + (size_t)s*(Hh/2)]);
    hh.x = fmaf(f.x, z.x - hh.x, hh.x);
    hh.y = fmaf(f.y, z.y - hh.y, hh.y);
    A.x *= (1.f - f.x);
    A.y *= (1.f - f.y);
  }
  int o = blockIdx.x*(Hh/2) + h2;
  ((float2*)g_Ac)[o] = A; ((float2*)g_Bc)[o] = hh;
}

__global__ __launch_bounds__(1024) void scanB_k(float* __restrict__ clast, int wr){
  int t = blockIdx.x*blockDim.x + threadIdx.x;   // 16384
  int b = t >> 10, h = t & (Hh-1);
  float hh = 0.f;
  #pragma unroll
  for (int c=0; c<SC; c++){
    int idx = (b*SC + c)*Hh + h;
    g_hs[idx] = hh;
    hh = fmaf(g_Ac[idx], hh, g_Bc[idx]);
  }
  if (wr) clast[t] = hh;
}

__global__ __launch_bounds__(512) void scanC_k(float* __restrict__ out){
  int b = blockIdx.x >> 4, c = blockIdx.x & 15, h2 = threadIdx.x;
  size_t base2 = ((size_t)(b*Ss + c*CH))*(Hh/2) + h2;
  const __half2* Z = (const __half2*)g_z;
  const __half2* F = (const __half2*)g_f;
  const __half2* O = (const __half2*)g_o;
  float2 hh = ((const float2*)g_hs)[blockIdx.x*(Hh/2) + h2];
  float2* out2 = (float2*)out;
  #pragma unroll 4
  for (int s=0; s<CH; s++){
    size_t idx = base2 + (size_t)s*(Hh/2);
    float2 f = __half22float2(F[idx]);
    float2 z = __half22float2(Z[idx]);
    float2 o = __half22float2(O[idx]);
    hh.x = fmaf(f.x, z.x - hh.x, hh.x);
    hh.y = fmaf(f.y, z.y - hh.y, hh.y);
    out2[idx] = make_float2(o.x*hh.x, o.y*hh.y);
  }
}

// ---- host ----
extern "C" void kernel_launch(void* const* d_in, const int* in_sizes, int n_in,
                              void* d_out, int out_size) {
  const float* inp  = (const float*)d_in[0];
  const float* W    = (const float*)d_in[1];
  const float* bias = (const float*)d_in[2];
  float* out = (float*)d_out;

  void *pA=nullptr, *pW=nullptr;
  cudaGetSymbolAddress(&pA, g_Ah);
  cudaGetSymbolAddress(&pW, g_Wh);

  int nA8 = Mm*Dd/8, nW8 = N3*Dd/8;
  to_half_k<<<(nA8+255)/256, 256>>>((const float4*)inp, (uint4*)pA, nA8);
  to_half_k<<<(nW8+255)/256, 256>>>((const float4*)W,   (uint4*)pW, nW8);

  static int smem_set = 0;
  if (!smem_set){
    cudaFuncSetAttribute(gemm_qrnn, cudaFuncAttributeMaxDynamicSharedMemorySize, GEMM_SMEM);
    smem_set = 1;
  }
  gemm_qrnn<<<dim3(N3/BN, Mm/BM), 256, GEMM_SMEM>>>((const __half*)pA, (const __half*)pW, bias);

  scanA_k<<<Bb*SC, 512>>>();
  int wr = (out_size >= Mm*Hh + Bb*Hh) ? 1 : 0;
  scanB_k<<<Bb*Hh/1024, 1024>>>(out + (size_t)Mm*Hh, wr);
  scanC_k<<<Bb*SC, 512>>>(out);
}